// round 1
// baseline (speedup 1.0000x reference)
#include <cuda_runtime.h>

// Problem constants
#define CCH 1024      // channels (c_in == c_out)
#define TT  4         // t dim
#define HWD 196       // 14*14
#define SSEG 4        // segments

// GEMM tiling
#define BM 128
#define BN 32
#define BK 32

// Pre-transposed weights: Wt[tap][ci][co], tap = ds*3+dt
__device__ float g_Wt[9 * CCH * CCH];

__global__ void wt_transpose_kernel(const float* __restrict__ W) {
    int idx = blockIdx.x * blockDim.x + threadIdx.x;   // 0 .. 9*1024*1024-1
    // dest layout: ((tap*1024 + ci)*1024 + co)
    int co  = idx & (CCH - 1);
    int ci  = (idx >> 10) & (CCH - 1);
    int tap = idx >> 20;
    // src layout: W[co][ci][tap] with tap stride 1, ci stride 9, co stride 9216
    g_Wt[idx] = W[(size_t)co * (CCH * 9) + ci * 9 + tap];
}

__global__ __launch_bounds__(256) void conv_seg_kernel(
    const float* __restrict__ x, float* __restrict__ out)
{
    const int pt  = blockIdx.x;       // 0..6   p-tile
    const int ct  = blockIdx.y;       // 0..7   co-tile
    const int z   = blockIdx.z;       // 0..31  (bi,ti)
    const int bi  = z >> 2;
    const int ti  = z & 3;
    const int s   = bi & 3;           // segment index within group
    const int bp  = bi >> 2;          // group index
    const int p0  = pt * BN;
    const int co0 = ct * BM;

    __shared__ float As[BK][BM];      // [k=ci][m=co]
    __shared__ float Bs[BK][BN];      // [k=ci][n=p]

    const int tid = threadIdx.x;
    const int tx  = tid & 15;         // N direction (16 lanes * 2 cols)
    const int ty  = tid >> 4;         // M direction (16 * 8 rows)

    float acc[8][2];
    #pragma unroll
    for (int r = 0; r < 8; r++) { acc[r][0] = 0.f; acc[r][1] = 0.f; }

    for (int ds = 0; ds < 3; ds++) {
        const int s2 = s + ds - 1;
        if (s2 < 0 || s2 >= SSEG) continue;
        for (int dt = 0; dt < 3; dt++) {
            const int t2 = ti + dt - 1;
            if (t2 < 0 || t2 >= TT) continue;

            const float* __restrict__ Wtap = g_Wt + (size_t)(ds * 3 + dt) * CCH * CCH;
            // x element (bi2, ci, t2, p) = x[bi2*C*T*HW + ci*T*HW + t2*HW + p]
            const float* __restrict__ xb =
                x + (size_t)(bp * SSEG + s2) * CCH * TT * HWD + (size_t)t2 * HWD;

            for (int k0 = 0; k0 < CCH; k0 += BK) {
                // ---- load A tile: 32 rows (ci) x 128 (co), co contiguous ----
                #pragma unroll
                for (int i = 0; i < 4; i++) {
                    int lin = tid + i * 256;        // float4 slot id, 0..1023
                    int kk  = lin >> 5;             // 0..31
                    int mm  = (lin & 31) << 2;      // 0..124 step 4
                    *(float4*)&As[kk][mm] =
                        *(const float4*)&Wtap[(size_t)(k0 + kk) * CCH + co0 + mm];
                }
                // ---- load B tile: 32 rows (ci) x 32 (p), p contiguous ----
                {
                    int kk = tid >> 5;              // warp id 0..7
                    int nn = tid & 31;              // lane
                    int p  = p0 + nn;
                    bool ok = (p < HWD);
                    #pragma unroll
                    for (int i = 0; i < 4; i++) {
                        int k = kk + i * 8;
                        Bs[k][nn] = ok ? xb[(size_t)(k0 + k) * (TT * HWD) + p] : 0.0f;
                    }
                }
                __syncthreads();

                #pragma unroll
                for (int k = 0; k < BK; k++) {
                    float4 a0 = *(float4*)&As[k][ty * 8];
                    float4 a1 = *(float4*)&As[k][ty * 8 + 4];
                    float2 b  = *(float2*)&Bs[k][tx * 2];
                    float av[8] = {a0.x, a0.y, a0.z, a0.w, a1.x, a1.y, a1.z, a1.w};
                    #pragma unroll
                    for (int r = 0; r < 8; r++) {
                        acc[r][0] += av[r] * b.x;
                        acc[r][1] += av[r] * b.y;
                    }
                }
                __syncthreads();
            }
        }
    }

    // ---- epilogue: residual add + store (p even, HW even -> float2 safe) ----
    const int p = p0 + tx * 2;
    if (p < HWD) {
        #pragma unroll
        for (int r = 0; r < 8; r++) {
            int co = co0 + ty * 8 + r;
            size_t oi = ((size_t)(bi * CCH + co) * TT + ti) * HWD + p;
            float2 xr = *(const float2*)&x[oi];
            float2 o;
            o.x = acc[r][0] + xr.x;
            o.y = acc[r][1] + xr.y;
            *(float2*)&out[oi] = o;
        }
    }
}

extern "C" void kernel_launch(void* const* d_in, const int* in_sizes, int n_in,
                              void* d_out, int out_size) {
    const float* x = (const float*)d_in[0];   // (8,1024,4,14,14)
    const float* W = (const float*)d_in[1];   // (1024,1024,3,3)
    float* out = (float*)d_out;

    // 1) transpose weights into g_Wt[tap][ci][co]
    {
        int total = 9 * CCH * CCH;
        wt_transpose_kernel<<<total / 256, 256>>>(W);
    }
    // 2) implicit-GEMM conv + residual
    {
        dim3 grid(7, CCH / BM, 32);   // p-tiles, co-tiles, (bi,ti)
        conv_seg_kernel<<<grid, 256>>>(x, out);
    }
}

// round 3
// speedup vs baseline: 3.3241x; 3.3241x over previous
#include <cuda_runtime.h>
#include <cstdint>

// ---------------------------------------------------------------------------
// y[bi,co,ti,p] = sum_{ds,dt,ci} W[co,ci,ds,dt]*x[bi',ci,t2,p] + x
// Implicit GEMM on tf32 mma.sync (m16n8k8) — tcgen05 unavailable because the
// harness PTX target is sm_100 (no 'a'); legacy HMMA + cp.async both compile.
// A = g_Wt[tap][co][ci] (K-major), B = g_Xt[z][p][ci] (K-major, p padded 224).
// CTA tile: 128(co) x 112(p), BK=32, double-buffered cp.async.
// ---------------------------------------------------------------------------

#define CCH 1024
#define TT 4
#define HW 196
#define NPAD 224
#define SSEG 4
#define BM 128
#define BN 112
#define BKI 32
#define PADW 36                       // smem row width in floats (conflict-free)

#define ASZ (BM * PADW)               // floats per A stage
#define BSZ (BN * PADW)
#define SMEM_FLOATS (2 * (ASZ + BSZ))
#define SMEM_REQ (SMEM_FLOATS * 4)    // 69120 B

__device__ float g_Wt[9u * CCH * CCH];      // [tap][co][ci], tf32-rounded
__device__ float g_Xt[32u * NPAD * CCH];    // [z][p][ci],    tf32-rounded, p>=196 zero

// ---------------------------- helpers --------------------------------------
__device__ __forceinline__ uint32_t f2tf32(float a) {
    uint32_t r; asm("cvt.rna.tf32.f32 %0, %1;" : "=r"(r) : "f"(a)); return r;
}
__device__ __forceinline__ void cp16(uint32_t dst, const void* src) {
    asm volatile("cp.async.cg.shared.global [%0], [%1], 16;" :: "r"(dst), "l"(src));
}
#define CP_COMMIT() asm volatile("cp.async.commit_group;" ::: "memory")
#define CP_WAIT1()  asm volatile("cp.async.wait_group 1;" ::: "memory")

__device__ __forceinline__ void mma_tf32(float* c, const uint32_t* a, const uint32_t* b) {
    asm volatile(
        "mma.sync.aligned.m16n8k8.row.col.f32.tf32.tf32.f32 "
        "{%0,%1,%2,%3}, {%4,%5,%6,%7}, {%8,%9}, {%0,%1,%2,%3};"
        : "+f"(c[0]), "+f"(c[1]), "+f"(c[2]), "+f"(c[3])
        : "r"(a[0]), "r"(a[1]), "r"(a[2]), "r"(a[3]), "r"(b[0]), "r"(b[1]));
}

// ---------------------------- prep kernels ---------------------------------
// g_Wt[tap][co][ci] = tf32(W[co][ci][tap])
__global__ __launch_bounds__(256) void prep_w(const float* __restrict__ W) {
    __shared__ float s[9216];
    int co = blockIdx.x;
    const float* row = W + (size_t)co * 9216;
    for (int i = threadIdx.x; i < 9216; i += 256) s[i] = row[i];
    __syncthreads();
    uint32_t* dst = (uint32_t*)g_Wt;
    for (int tap = 0; tap < 9; tap++) {
        uint32_t* d = dst + ((size_t)tap * CCH + co) * CCH;
        for (int ci = threadIdx.x; ci < CCH; ci += 256)
            d[ci] = f2tf32(s[ci * 9 + tap]);
    }
}

// g_Xt[z][p][ci] = tf32(x[bi][ci][t][p]); p in [196,224) -> 0
__global__ void prep_x(const float* __restrict__ x) {
    __shared__ float tile[32][33];
    int z = blockIdx.z;                    // bi*4 + t
    int p0 = blockIdx.x * 32;              // 7 tiles -> 224
    int ci0 = blockIdx.y * 32;
    int tx = threadIdx.x, ty = threadIdx.y;   // 32 x 8
    #pragma unroll
    for (int j = 0; j < 4; j++) {
        int ci = ci0 + ty + j * 8;
        int p = p0 + tx;
        float v = 0.f;
        if (p < HW) v = x[(((size_t)((z >> 2) * CCH + ci)) * TT + (z & 3)) * HW + p];
        tile[ty + j * 8][tx] = v;
    }
    __syncthreads();
    uint32_t* dst = (uint32_t*)g_Xt;
    #pragma unroll
    for (int j = 0; j < 4; j++) {
        int p = p0 + ty + j * 8;
        int ci = ci0 + tx;
        dst[((size_t)z * NPAD + p) * CCH + ci] = f2tf32(tile[tx][ty + j * 8]);
    }
}

// ---------------------------- main kernel -----------------------------------
__global__ __launch_bounds__(256, 2) void conv_mma(
    const float* __restrict__ x, float* __restrict__ out)
{
    extern __shared__ float smem[];
    const int tid = threadIdx.x;
    const int wid = tid >> 5, lid = tid & 31;
    const int gid = lid >> 2, tig = lid & 3;
    const int warp_m = wid & 3;           // 4 warps in M: 32 rows each
    const int warp_n = wid >> 2;          // 2 warps in N: 56 cols each

    const int ct = blockIdx.x >> 1;       // co tile 0..7
    const int py = blockIdx.x & 1;        // p tile 0..1
    const int z  = blockIdx.y;            // bi*4 + ti
    const int bi = z >> 2, ti = z & 3;
    const int s_seg = bi & 3, bp = bi >> 2;
    const int co0 = ct * BM;
    const int p0  = py * BN;

    // valid taps
    int taps[9], zsrc[9], nv = 0;
    #pragma unroll
    for (int ds = 0; ds < 3; ds++) {
        int s2 = s_seg + ds - 1;
        if (s2 < 0 || s2 >= SSEG) continue;
        #pragma unroll
        for (int dt = 0; dt < 3; dt++) {
            int t2 = ti + dt - 1;
            if (t2 < 0 || t2 >= TT) continue;
            taps[nv] = ds * 3 + dt;
            zsrc[nv] = (bp * SSEG + s2) * TT + t2;
            nv++;
        }
    }
    const int total = nv * (CCH / BKI);

    uint32_t smem_u = (uint32_t)__cvta_generic_to_shared(smem);
    const uint32_t aB[2] = { smem_u, smem_u + ASZ * 4 };
    const uint32_t bB[2] = { smem_u + 2 * ASZ * 4, smem_u + (2 * ASZ + BSZ) * 4 };

    float acc[2][7][4];
    #pragma unroll
    for (int mt = 0; mt < 2; mt++)
        #pragma unroll
        for (int nt = 0; nt < 7; nt++)
            #pragma unroll
            for (int r = 0; r < 4; r++) acc[mt][nt][r] = 0.f;

    // stage loader: A 1024 16B chunks, B 896 chunks
    auto load_stage = [&](int it, int s) {
        int idx = it >> 5, k0 = (it & 31) * BKI;
        const float* Wt = g_Wt + (size_t)taps[idx] * CCH * CCH + (size_t)co0 * CCH + k0;
        const float* Xz = g_Xt + (size_t)zsrc[idx] * NPAD * CCH + (size_t)p0 * CCH + k0;
        #pragma unroll
        for (int i = 0; i < 4; i++) {
            int c = tid + i * 256;
            int row = c >> 3, cc = c & 7;
            cp16(aB[s] + row * (PADW * 4) + cc * 16, Wt + (size_t)row * CCH + cc * 4);
        }
        #pragma unroll
        for (int i = 0; i < 4; i++) {
            int c = tid + i * 256;
            if (c < BN * 8) {
                int row = c >> 3, cc = c & 7;
                cp16(bB[s] + row * (PADW * 4) + cc * 16, Xz + (size_t)row * CCH + cc * 4);
            }
        }
    };

    load_stage(0, 0);
    CP_COMMIT();

    for (int it = 0; it < total; it++) {
        int s = it & 1;
        if (it + 1 < total) load_stage(it + 1, s ^ 1);
        CP_COMMIT();
        CP_WAIT1();
        __syncthreads();

        const float* As = smem + s * ASZ;
        const float* Bs = smem + 2 * ASZ + s * BSZ;
        #pragma unroll
        for (int ks = 0; ks < 4; ks++) {
            int k = ks * 8 + tig;
            uint32_t a[2][4], b[7][2];
            #pragma unroll
            for (int mt = 0; mt < 2; mt++) {
                const uint32_t* ap = (const uint32_t*)(As + (warp_m * 32 + mt * 16 + gid) * PADW + k);
                a[mt][0] = ap[0];
                a[mt][1] = ap[8 * PADW];
                a[mt][2] = ap[4];
                a[mt][3] = ap[8 * PADW + 4];
            }
            #pragma unroll
            for (int nt = 0; nt < 7; nt++) {
                const uint32_t* bp2 = (const uint32_t*)(Bs + (warp_n * 56 + nt * 8 + gid) * PADW + k);
                b[nt][0] = bp2[0];
                b[nt][1] = bp2[4];
            }
            #pragma unroll
            for (int mt = 0; mt < 2; mt++)
                #pragma unroll
                for (int nt = 0; nt < 7; nt++)
                    mma_tf32(acc[mt][nt], a[mt], b[nt]);
        }
        __syncthreads();
    }

    // epilogue: residual add + store
    #pragma unroll
    for (int mt = 0; mt < 2; mt++) {
        #pragma unroll
        for (int nt = 0; nt < 7; nt++) {
            int co = co0 + warp_m * 32 + mt * 16 + gid;
            int p  = p0 + warp_n * 56 + nt * 8 + tig * 2;
            if (p < HW) {
                size_t i0 = ((size_t)(bi * CCH + co) * TT + ti) * HW + p;
                float2 r0 = *(const float2*)&x[i0];
                float2 o0 = { acc[mt][nt][0] + r0.x, acc[mt][nt][1] + r0.y };
                *(float2*)&out[i0] = o0;
                size_t i1 = ((size_t)(bi * CCH + co + 8) * TT + ti) * HW + p;
                float2 r1 = *(const float2*)&x[i1];
                float2 o1 = { acc[mt][nt][2] + r1.x, acc[mt][nt][3] + r1.y };
                *(float2*)&out[i1] = o1;
            }
        }
    }
}

// ---------------------------- host launch -----------------------------------
extern "C" void kernel_launch(void* const* d_in, const int* in_sizes, int n_in,
                              void* d_out, int out_size) {
    const float* x = (const float*)d_in[0];   // (8,1024,4,14,14)
    const float* W = (const float*)d_in[1];   // (1024,1024,3,3)
    float* out = (float*)d_out;

    prep_w<<<CCH, 256>>>(W);
    prep_x<<<dim3(7, 32, 32), dim3(32, 8)>>>(x);

    cudaFuncSetAttribute(conv_mma, cudaFuncAttributeMaxDynamicSharedMemorySize, SMEM_REQ);
    conv_mma<<<dim3(16, 32), 256, SMEM_REQ>>>(x, out);
}